// round 4
// baseline (speedup 1.0000x reference)
#include <cuda_runtime.h>
#include <cuda_bf16.h>
#include <math.h>

// ---------------------------------------------------------------------------
// Problem constants
// ---------------------------------------------------------------------------
#define N_NOTES   64
#define N_WORDS   256
#define BATCH     32
#define WDIM      128
#define OC        256
#define FW        3
#define HID       256
#define L_OUT     258          // N_WORDS + 2*(FW-1) - FW + 1
#define KDIM      384          // FW * WDIM

#define ET_STRIDE 260          // smem row stride for E_T (>=260 cols, mult of 4)

// Output layout (float32):
//   out_note          [64][32][512]   offset 0        (1,048,576)
//   note_attn_norm    [32][64]        offset 1,048,576 (2,048)
//   note_attn_vectors [32][512]       offset 1,050,624 (16,384)
//   final_map         [32][2]         offset 1,067,008 (64)
#define OFF_NORM 1048576
#define OFF_VEC  1050624
#define OFF_FIN  1067008

// ---------------------------------------------------------------------------
// Scratch (device globals; no dynamic allocation allowed)
// ---------------------------------------------------------------------------
__device__ float g_feat[N_NOTES * BATCH * OC];              // 2 MB
__device__ float g_gi[2 * N_NOTES * BATCH * 3 * HID];       // 12.6 MB
__device__ float g_WT[512 * 512];                           // 1 MB  (W_note^T)
__device__ float g_attn[N_NOTES * BATCH];                   // 8 KB

// ---------------------------------------------------------------------------
// Kernel 1: embedding gather + conv + tanh + max-pool  ->  g_feat[n][b][oc]
// One CTA per (note n, batch b).  256 threads.
// smem: E_T[128][260] | Ws[32][256] | red[16][256] | smax[256]
// ---------------------------------------------------------------------------
#define CONV_SMEM ((128*ET_STRIDE + 32*256 + 16*256 + 256) * 4)

__global__ void __launch_bounds__(256, 1) conv_feat_kernel(
    const int*   __restrict__ mini_batch,   // [64][256][32]
    const float* __restrict__ embed_table,  // [50000][128]
    const float* __restrict__ conv_w,       // [256][384]
    const float* __restrict__ conv_b)       // [256]
{
    extern __shared__ float smem[];
    float* ET   = smem;                        // 128 x 260
    float* Ws   = smem + 128 * ET_STRIDE;      // 32 x 256  (W chunk, transposed)
    float* red  = Ws   + 32 * 256;             // 16 x 256
    float* smax = red  + 16 * 256;             // 256

    const int tid = threadIdx.x;
    const int n = blockIdx.x >> 5;
    const int b = blockIdx.x & 31;

    // ---- zero E_T, init maxes ----
    for (int i = tid; i < 128 * ET_STRIDE; i += 256) ET[i] = 0.0f;
    smax[tid] = -1e30f;
    __syncthreads();

    // ---- gather: E_T[d][w+2] = embed_table[tok(n,w,b)][d] ----
    {
        const int warp = tid >> 5, lane = tid & 31;
        for (int wi = 0; wi < 32; wi++) {
            const int w   = wi * 8 + warp;
            const int tok = mini_batch[(n * N_WORDS + w) * BATCH + b];
            const float* er = embed_table + (long)tok * WDIM;
#pragma unroll
            for (int j = 0; j < 4; j++) {
                const int d = lane + 32 * j;
                ET[d * ET_STRIDE + (w + 2)] = er[d];
            }
        }
    }
    __syncthreads();

    // ---- GEMM: z[l][oc] = sum_k A_T[k][l] * W[oc][k];  A_T[k][l] = E_T[k%128][l + k/128]
    const int lt = tid >> 4;   // 0..15 -> l group (4 consecutive l's)
    const int ot = tid & 15;   // 0..15 -> oc group (oc = ot*4 + 64*j + jj)

    for (int ltile = 0; ltile < 256; ltile += 64) {
        float acc[4][16];
#pragma unroll
        for (int i = 0; i < 4; i++)
#pragma unroll
            for (int j = 0; j < 16; j++) acc[i][j] = 0.0f;

        for (int kc = 0; kc < 12; kc++) {
            __syncthreads();
            // load W chunk k in [kc*32, kc*32+32), transposed: Ws[kk][oc]
            {
                const float* wp = conv_w + tid * KDIM + kc * 32;
#pragma unroll
                for (int q = 0; q < 8; q++) {
                    float4 v = *(const float4*)(wp + q * 4);
                    Ws[(q * 4 + 0) * 256 + tid] = v.x;
                    Ws[(q * 4 + 1) * 256 + tid] = v.y;
                    Ws[(q * 4 + 2) * 256 + tid] = v.z;
                    Ws[(q * 4 + 3) * 256 + tid] = v.w;
                }
            }
            __syncthreads();
#pragma unroll 4
            for (int kk = 0; kk < 32; kk++) {
                const int k  = kc * 32 + kk;
                const int d  = k & 127;
                const int sh = k >> 7;
                const float* ar = ET + d * ET_STRIDE + ltile + (lt << 2) + sh;
                const float a0 = ar[0], a1 = ar[1], a2 = ar[2], a3 = ar[3];
                const float* wr = Ws + kk * 256 + (ot << 2);
#pragma unroll
                for (int j = 0; j < 4; j++) {
                    float4 w4 = *(const float4*)(wr + j * 64);
                    acc[0][j*4+0] += a0 * w4.x;  acc[1][j*4+0] += a1 * w4.x;
                    acc[2][j*4+0] += a2 * w4.x;  acc[3][j*4+0] += a3 * w4.x;
                    acc[0][j*4+1] += a0 * w4.y;  acc[1][j*4+1] += a1 * w4.y;
                    acc[2][j*4+1] += a2 * w4.y;  acc[3][j*4+1] += a3 * w4.y;
                    acc[0][j*4+2] += a0 * w4.z;  acc[1][j*4+2] += a1 * w4.z;
                    acc[2][j*4+2] += a2 * w4.z;  acc[3][j*4+2] += a3 * w4.z;
                    acc[0][j*4+3] += a0 * w4.w;  acc[1][j*4+3] += a1 * w4.w;
                    acc[2][j*4+3] += a2 * w4.w;  acc[3][j*4+3] += a3 * w4.w;
                }
            }
        }
        // per-thread max over its 4 l's, reduce across lt via smem
#pragma unroll
        for (int j = 0; j < 16; j++) {
            float m = fmaxf(fmaxf(acc[0][j], acc[1][j]), fmaxf(acc[2][j], acc[3][j]));
            const int oc = (ot << 2) + ((j >> 2) << 6) + (j & 3);
            red[lt * 256 + oc] = m;
        }
        __syncthreads();
        {
            float m = smax[tid];
#pragma unroll
            for (int q = 0; q < 16; q++) m = fmaxf(m, red[q * 256 + tid]);
            smax[tid] = m;
        }
        __syncthreads();
    }

    // ---- epilogue: l = 256, 257 (scalar path, oc = tid) ----
    {
        float a0 = 0.0f, a1 = 0.0f;
        const float* wr = conv_w + tid * KDIM;
#pragma unroll 1
        for (int seg = 0; seg < 3; seg++) {
            const float* ec = ET + 256 + seg;     // col 256+seg (l=256), +1 -> l=257
#pragma unroll 8
            for (int d4 = 0; d4 < 32; d4++) {
                float4 w4 = *(const float4*)(wr + seg * 128 + d4 * 4);
                const int d = d4 * 4;
                a0 += w4.x * ec[(d + 0) * ET_STRIDE];
                a1 += w4.x * ec[(d + 0) * ET_STRIDE + 1];
                a0 += w4.y * ec[(d + 1) * ET_STRIDE];
                a1 += w4.y * ec[(d + 1) * ET_STRIDE + 1];
                a0 += w4.z * ec[(d + 2) * ET_STRIDE];
                a1 += w4.z * ec[(d + 2) * ET_STRIDE + 1];
                a0 += w4.w * ec[(d + 3) * ET_STRIDE];
                a1 += w4.w * ec[(d + 3) * ET_STRIDE + 1];
            }
        }
        const float m = fmaxf(smax[tid], fmaxf(a0, a1));
        g_feat[(n * BATCH + b) * OC + tid] = tanhf(conv_b[tid] + m);
    }
}

// ---------------------------------------------------------------------------
// Kernel 2: gi = feat @ w_ih^T + b_ih  for both directions
// CTA = (dir, n); 256 threads; thread -> gate rows {tid, tid+256, tid+512}
// ---------------------------------------------------------------------------
__global__ void __launch_bounds__(256) gi_kernel(
    const float* __restrict__ w_ih_f, const float* __restrict__ w_ih_b,
    const float* __restrict__ b_ih_f, const float* __restrict__ b_ih_b)
{
    __shared__ float As[BATCH * OC];            // 32 x 256
    const int tid = threadIdx.x;
    const int dir = blockIdx.x >> 6;
    const int n   = blockIdx.x & 63;

    const float* feat = g_feat + n * BATCH * OC;
    for (int i = tid; i < (BATCH * OC) / 4; i += 256)
        ((float4*)As)[i] = ((const float4*)feat)[i];

    const float* W  = dir ? w_ih_b : w_ih_f;
    const float* bi = dir ? b_ih_b : b_ih_f;
    const float* w0 = W + (tid      ) * OC;
    const float* w1 = W + (tid + 256) * OC;
    const float* w2 = W + (tid + 512) * OC;

    float acc0[32], acc1[32], acc2[32];
#pragma unroll
    for (int bb = 0; bb < 32; bb++) { acc0[bb] = 0.f; acc1[bb] = 0.f; acc2[bb] = 0.f; }
    __syncthreads();

    for (int k4 = 0; k4 < OC / 4; k4++) {
        const float4 v0 = *(const float4*)(w0 + k4 * 4);
        const float4 v1 = *(const float4*)(w1 + k4 * 4);
        const float4 v2 = *(const float4*)(w2 + k4 * 4);
#pragma unroll
        for (int bb = 0; bb < 32; bb++) {
            const float4 a = *(const float4*)&As[bb * OC + k4 * 4];
            acc0[bb] += v0.x * a.x + v0.y * a.y + v0.z * a.z + v0.w * a.w;
            acc1[bb] += v1.x * a.x + v1.y * a.y + v1.z * a.z + v1.w * a.w;
            acc2[bb] += v2.x * a.x + v2.y * a.y + v2.z * a.z + v2.w * a.w;
        }
    }
    const float bi0 = bi[tid], bi1 = bi[tid + 256], bi2 = bi[tid + 512];
    float* go = g_gi + (size_t)((dir * N_NOTES + n) * BATCH) * 768;
#pragma unroll 4
    for (int bb = 0; bb < 32; bb++) {
        go[bb * 768 +       tid] = acc0[bb] + bi0;
        go[bb * 768 + 256 + tid] = acc1[bb] + bi1;
        go[bb * 768 + 512 + tid] = acc2[bb] + bi2;
    }
}

// ---------------------------------------------------------------------------
// Kernel 3: GRU recurrence. CTA = (dir, b) -> 64 independent chains.
// Writes out_note directly into d_out.
// ---------------------------------------------------------------------------
__global__ void __launch_bounds__(256) gru_kernel(
    const float* __restrict__ w_hh_f, const float* __restrict__ w_hh_b,
    const float* __restrict__ b_hh_f, const float* __restrict__ b_hh_b,
    const float* __restrict__ hidden_state,
    float* __restrict__ out)
{
    __shared__ float h[HID];
    const int i   = threadIdx.x;
    const int dir = blockIdx.x >> 5;
    const int b   = blockIdx.x & 31;

    const float* whh = dir ? w_hh_b : w_hh_f;
    const float* bhh = dir ? b_hh_b : b_hh_f;

    h[i] = hidden_state[(dir * BATCH + b) * HID + i];
    const float bh0 = bhh[i], bh1 = bhh[i + 256], bh2 = bhh[i + 512];
    const float* w0 = whh + (i      ) * HID;
    const float* w1 = whh + (i + 256) * HID;
    const float* w2 = whh + (i + 512) * HID;
    __syncthreads();

    for (int s = 0; s < N_NOTES; s++) {
        const int n = dir ? (N_NOTES - 1 - s) : s;
        float g0 = bh0, g1 = bh1, g2 = bh2;
#pragma unroll 4
        for (int k4 = 0; k4 < HID / 4; k4++) {
            const float4 hv = *(const float4*)&h[k4 * 4];
            const float4 a = *(const float4*)(w0 + k4 * 4);
            const float4 c = *(const float4*)(w1 + k4 * 4);
            const float4 e = *(const float4*)(w2 + k4 * 4);
            g0 += a.x * hv.x + a.y * hv.y + a.z * hv.z + a.w * hv.w;
            g1 += c.x * hv.x + c.y * hv.y + c.z * hv.z + c.w * hv.w;
            g2 += e.x * hv.x + e.y * hv.y + e.z * hv.z + e.w * hv.w;
        }
        const float* gp = g_gi + (size_t)((dir * N_NOTES + n) * BATCH + b) * 768;
        const float r  = 1.0f / (1.0f + expf(-(gp[i]       + g0)));
        const float z  = 1.0f / (1.0f + expf(-(gp[i + 256] + g1)));
        const float nn = tanhf(gp[i + 512] + r * g2);
        const float hn = (1.0f - z) * nn + z * h[i];
        __syncthreads();
        h[i] = hn;
        __syncthreads();
        out[(size_t)(n * BATCH + b) * 512 + dir * HID + i] = hn;
    }
}

// ---------------------------------------------------------------------------
// Kernel 4a: transpose W_note -> g_WT[e][d]
// ---------------------------------------------------------------------------
__global__ void __launch_bounds__(256) wnote_transpose_kernel(const float* __restrict__ W)
{
    const int e = blockIdx.x;
    for (int d = threadIdx.x; d < 512; d += 256)
        g_WT[e * 512 + d] = W[d * 512 + e];
}

// ---------------------------------------------------------------------------
// Kernel 4b: attn[n][b] = sum_e tanh(out_note[n][b]·W_note[:,e] + bias[e]) * proj[e]
// CTA per n; smem holds out_note[n] (32x512); thread handles e = tid, tid+256.
// ---------------------------------------------------------------------------
__global__ void __launch_bounds__(256) attn_kernel(
    const float* __restrict__ out_note,
    const float* __restrict__ bias_note,
    const float* __restrict__ proj_note)
{
    extern __shared__ float As[];               // 32 x 512
    __shared__ float wred[8][32];
    const int tid = threadIdx.x;
    const int n = blockIdx.x;

    const float* src = out_note + (size_t)n * BATCH * 512;
    for (int i = tid; i < (BATCH * 512) / 4; i += 256)
        ((float4*)As)[i] = ((const float4*)src)[i];

    float attnacc[32];
#pragma unroll
    for (int bb = 0; bb < 32; bb++) attnacc[bb] = 0.0f;
    __syncthreads();

    for (int ee = 0; ee < 2; ee++) {
        const int e = ee * 256 + tid;
        const float* w = g_WT + e * 512;
        float acc[32];
#pragma unroll
        for (int bb = 0; bb < 32; bb++) acc[bb] = 0.0f;
        for (int d4 = 0; d4 < 128; d4++) {
            const float4 wv = *(const float4*)(w + d4 * 4);
#pragma unroll
            for (int bb = 0; bb < 32; bb++) {
                const float4 a = *(const float4*)&As[bb * 512 + d4 * 4];
                acc[bb] += wv.x * a.x + wv.y * a.y + wv.z * a.z + wv.w * a.w;
            }
        }
        const float be = bias_note[e], pe = proj_note[e];
#pragma unroll
        for (int bb = 0; bb < 32; bb++)
            attnacc[bb] += tanhf(acc[bb] + be) * pe;
    }
    // reduce across 256 threads: butterfly within warp, then across warps
#pragma unroll
    for (int off = 16; off; off >>= 1)
#pragma unroll
        for (int bb = 0; bb < 32; bb++)
            attnacc[bb] += __shfl_xor_sync(0xffffffffu, attnacc[bb], off);
    const int wid = tid >> 5, lane = tid & 31;
    if (lane == 0)
#pragma unroll
        for (int bb = 0; bb < 32; bb++) wred[wid][bb] = attnacc[bb];
    __syncthreads();
    if (tid < 32) {
        float s = 0.0f;
#pragma unroll
        for (int w = 0; w < 8; w++) s += wred[w][tid];
        g_attn[n * BATCH + tid] = s;
    }
}

// ---------------------------------------------------------------------------
// Kernel 5: softmax over notes, weighted sum, final linear. CTA per b.
// ---------------------------------------------------------------------------
__global__ void __launch_bounds__(256) final_kernel(
    const float* __restrict__ out_note,
    const float* __restrict__ lin_w,
    const float* __restrict__ lin_b,
    float* __restrict__ out)
{
    __shared__ float sa[64];
    __shared__ float vec[512];
    __shared__ float stats[2];
    const int tid = threadIdx.x;
    const int b = blockIdx.x;

    if (tid < 64) sa[tid] = g_attn[tid * BATCH + b];
    __syncthreads();
    if (tid < 32) {
        const float v0 = sa[tid], v1 = sa[tid + 32];
        float m = fmaxf(v0, v1);
#pragma unroll
        for (int o = 16; o; o >>= 1) m = fmaxf(m, __shfl_xor_sync(0xffffffffu, m, o));
        float s = expf(v0 - m) + expf(v1 - m);
#pragma unroll
        for (int o = 16; o; o >>= 1) s += __shfl_xor_sync(0xffffffffu, s, o);
        if (tid == 0) { stats[0] = m; stats[1] = s; }
    }
    __syncthreads();
    if (tid < 64) {
        const float nv = expf(sa[tid] - stats[0]) / stats[1];
        sa[tid] = nv;
        out[OFF_NORM + b * 64 + tid] = nv;
    }
    __syncthreads();
#pragma unroll
    for (int dd = 0; dd < 2; dd++) {
        const int d = dd * 256 + tid;
        float acc = 0.0f;
#pragma unroll 8
        for (int n = 0; n < 64; n++)
            acc += sa[n] * out_note[(size_t)(n * BATCH + b) * 512 + d];
        vec[d] = acc;
        out[OFF_VEC + b * 512 + d] = acc;
    }
    __syncthreads();
    if (tid < 64) {
        const int c = tid >> 5, lane = tid & 31;
        float p = 0.0f;
#pragma unroll 4
        for (int i = lane; i < 512; i += 32) p += lin_w[c * 512 + i] * vec[i];
#pragma unroll
        for (int o = 16; o; o >>= 1) p += __shfl_xor_sync(0xffffffffu, p, o);
        if (lane == 0) out[OFF_FIN + b * 2 + c] = p + lin_b[c];
    }
}

// ---------------------------------------------------------------------------
// Launcher
// ---------------------------------------------------------------------------
extern "C" void kernel_launch(void* const* d_in, const int* in_sizes, int n_in,
                              void* d_out, int out_size)
{
    (void)in_sizes; (void)n_in; (void)out_size;
    const int*   mini_batch = (const int*)d_in[0];
    const float* hidden     = (const float*)d_in[1];
    const float* embed      = (const float*)d_in[2];
    const float* conv_w     = (const float*)d_in[3];
    const float* conv_b     = (const float*)d_in[4];
    const float* w_ih_f     = (const float*)d_in[5];
    const float* w_hh_f     = (const float*)d_in[6];
    const float* b_ih_f     = (const float*)d_in[7];
    const float* b_hh_f     = (const float*)d_in[8];
    const float* w_ih_b     = (const float*)d_in[9];
    const float* w_hh_b     = (const float*)d_in[10];
    const float* b_ih_b     = (const float*)d_in[11];
    const float* b_hh_b     = (const float*)d_in[12];
    const float* W_note     = (const float*)d_in[13];
    const float* bias_note  = (const float*)d_in[14];
    const float* proj_note  = (const float*)d_in[15];
    const float* lin_w      = (const float*)d_in[16];
    const float* lin_b      = (const float*)d_in[17];
    float* out = (float*)d_out;

    cudaFuncSetAttribute(conv_feat_kernel,
                         cudaFuncAttributeMaxDynamicSharedMemorySize, CONV_SMEM);
    cudaFuncSetAttribute(attn_kernel,
                         cudaFuncAttributeMaxDynamicSharedMemorySize, 65536);

    conv_feat_kernel<<<N_NOTES * BATCH, 256, CONV_SMEM>>>(mini_batch, embed, conv_w, conv_b);
    wnote_transpose_kernel<<<512, 256>>>(W_note);
    gi_kernel<<<128, 256>>>(w_ih_f, w_ih_b, b_ih_f, b_ih_b);
    gru_kernel<<<64, 256>>>(w_hh_f, w_hh_b, b_hh_f, b_hh_b, hidden, out);
    attn_kernel<<<64, 256, 65536>>>(out, bias_note, proj_note);
    final_kernel<<<32, 256>>>(out, lin_w, lin_b, out);
}

// round 5
// speedup vs baseline: 1.6245x; 1.6245x over previous
#include <cuda_runtime.h>
#include <cuda_bf16.h>
#include <math.h>

// ---------------------------------------------------------------------------
// Problem constants
// ---------------------------------------------------------------------------
#define N_NOTES   64
#define N_WORDS   256
#define BATCH     32
#define WDIM      128
#define OC        256
#define HID       256

// Output layout (float32)
#define OFF_NORM 1048576
#define OFF_VEC  1050624
#define OFF_FIN  1067008

// ---------------------------------------------------------------------------
// Scratch (device globals)
// ---------------------------------------------------------------------------
__device__ unsigned int  g_featmax[N_NOTES * BATCH * OC];    // order-encoded max
__device__ float         g_gi[2 * N_NOTES * BATCH * 3 * HID];
__device__ float         g_WT[512 * 512];
__device__ float         g_attn[N_NOTES * BATCH];
__device__ __nv_bfloat16 g_Bhi[384 * 264];                   // W^T split hi  [k][n]
__device__ __nv_bfloat16 g_Blo[384 * 264];                   // W^T split lo  [k][n]

// ---------------------------------------------------------------------------
// PTX helpers
// ---------------------------------------------------------------------------
__device__ __forceinline__ void ldm_x4(unsigned* r, unsigned addr) {
    asm volatile("ldmatrix.sync.aligned.m8n8.x4.shared.b16 {%0,%1,%2,%3},[%4];"
        : "=r"(r[0]), "=r"(r[1]), "=r"(r[2]), "=r"(r[3]) : "r"(addr));
}
__device__ __forceinline__ void ldm_x4t(unsigned* r, unsigned addr) {
    asm volatile("ldmatrix.sync.aligned.m8n8.x4.trans.shared.b16 {%0,%1,%2,%3},[%4];"
        : "=r"(r[0]), "=r"(r[1]), "=r"(r[2]), "=r"(r[3]) : "r"(addr));
}
__device__ __forceinline__ void mma16816(float* c, const unsigned* a, const unsigned* b) {
    asm volatile("mma.sync.aligned.m16n8k16.row.col.f32.bf16.bf16.f32 "
        "{%0,%1,%2,%3},{%4,%5,%6,%7},{%8,%9},{%0,%1,%2,%3};"
        : "+f"(c[0]), "+f"(c[1]), "+f"(c[2]), "+f"(c[3])
        : "r"(a[0]), "r"(a[1]), "r"(a[2]), "r"(a[3]), "r"(b[0]), "r"(b[1]));
}
__device__ __forceinline__ void cp16(unsigned dst, const void* src) {
    asm volatile("cp.async.cg.shared.global [%0],[%1],16;" :: "r"(dst), "l"(src));
}
__device__ __forceinline__ void cp_commit() { asm volatile("cp.async.commit_group;"); }
template<int N> __device__ __forceinline__ void cp_wait() {
    asm volatile("cp.async.wait_group %0;" :: "n"(N));
}

// ---------------------------------------------------------------------------
// Kernel 0a: init featmax keys to 0 (= minimum key)
// ---------------------------------------------------------------------------
__global__ void init_featmax_kernel() {
    g_featmax[blockIdx.x * 256 + threadIdx.x] = 0u;
}

// ---------------------------------------------------------------------------
// Kernel 0b: split + transpose conv_w[oc][k] -> g_Bhi/g_Blo [k][n=oc] (bf16 pair)
// ---------------------------------------------------------------------------
__global__ void __launch_bounds__(256) wsplit_kernel(const float* __restrict__ conv_w) {
    const int k = blockIdx.x;          // 0..383
    const int n = threadIdx.x;         // 0..255
    float v = conv_w[n * 384 + k];
    __nv_bfloat16 hi = __float2bfloat16(v);
    __nv_bfloat16 lo = __float2bfloat16(v - __bfloat162float(hi));
    g_Bhi[k * 264 + n] = hi;
    g_Blo[k * 264 + n] = lo;
}

// ---------------------------------------------------------------------------
// Kernel 1: conv as bf16x3-split tensor-core GEMM + fused max-pool.
// CTA = (sample, l-half). M=128 (+ masked tail tile on upper half), N=256, K=384.
// ---------------------------------------------------------------------------
#define ES      136        // E smem row stride (halfs); 272B rows
#define BS      264        // B row stride (halfs); 528B rows
#define EROWS   148
#define EHI_OFF 0
#define ELO_OFF 40256
#define BHI_OFF 80512
#define BLO_OFF 114304
#define WMAX_OFF 148096
#define TOK_OFF  157312
#define CONV2_SMEM 157904
#define BSTAGE  16896      // 32 rows * 264 halfs * 2B

__global__ void __launch_bounds__(256, 1) conv_mma_kernel(
    const int*   __restrict__ mini_batch,   // [64][256][32]
    const float* __restrict__ embed)        // [50000][128]
{
    extern __shared__ char sm[];
    const unsigned smu = (unsigned)__cvta_generic_to_shared(sm);
    const int tid = threadIdx.x, lane = tid & 31, w = tid >> 5;
    const int sample = blockIdx.x >> 1;
    const int half   = blockIdx.x & 1;
    const int l0     = half << 7;
    const int n = sample >> 5, b = sample & 31;
    const bool extra = (half == 1);

    int*   tok_s = (int*)(sm + TOK_OFF);
    float* wmax  = (float*)(sm + WMAX_OFF);
    const float NEG = __int_as_float(0xff800000);  // -inf

    // prefetch B chunk 0 (both hi & lo)
    {
        const char* sH = (const char*)g_Bhi;
        const char* sL = (const char*)g_Blo;
        for (int i = tid; i < 1056; i += 256) {
            cp16(smu + BHI_OFF + i * 16, sH + i * 16);
            cp16(smu + BLO_OFF + i * 16, sL + i * 16);
        }
        cp_commit();
    }

    // tokens for E_pad rows l0..l0+147  (word = row-2)
    if (tid < EROWS) {
        int word = l0 + tid - 2;
        tok_s[tid] = (word >= 0 && word < N_WORDS)
                   ? mini_batch[(n * N_WORDS + word) * BATCH + b] : -1;
    }
    for (int i = tid; i < 9 * 256; i += 256) wmax[i] = NEG;
    __syncthreads();

    // build E hi/lo (bf16 split of gathered embeddings; zero rows for padding)
    for (int i = tid; i < EROWS * 64; i += 256) {
        const int row = i >> 6, p = i & 63;
        const int t = tok_s[row];
        __nv_bfloat162 hv, lv;
        if (t >= 0) {
            float2 v = *(const float2*)(embed + (size_t)t * WDIM + p * 2);
            __nv_bfloat16 h0 = __float2bfloat16(v.x);
            __nv_bfloat16 h1 = __float2bfloat16(v.y);
            hv = __halves2bfloat162(h0, h1);
            lv = __halves2bfloat162(__float2bfloat16(v.x - __bfloat162float(h0)),
                                    __float2bfloat16(v.y - __bfloat162float(h1)));
        } else {
            hv = __float2bfloat162_rn(0.0f);
            lv = hv;
        }
        *(__nv_bfloat162*)(sm + EHI_OFF + (row * ES + 2 * p) * 2) = hv;
        *(__nv_bfloat162*)(sm + ELO_OFF + (row * ES + 2 * p) * 2) = lv;
    }

    float cm[16][2][4];
#pragma unroll
    for (int i = 0; i < 16; i++)
#pragma unroll
        for (int s = 0; s < 2; s++)
#pragma unroll
            for (int r = 0; r < 4; r++) cm[i][s][r] = 0.0f;
    float cx[2][2][4];
#pragma unroll
    for (int i = 0; i < 2; i++)
#pragma unroll
        for (int s = 0; s < 2; s++)
#pragma unroll
            for (int r = 0; r < 4; r++) cx[i][s][r] = 0.0f;

    // ---- main loop over 12 k-chunks of 32 ----
    for (int chunk = 0; chunk < 12; chunk++) {
        const int stage = chunk & 1;
        if (chunk + 1 < 12) {
            const int nc = chunk + 1, ns = nc & 1;
            const char* sH = (const char*)(g_Bhi + nc * 32 * BS);
            const char* sL = (const char*)(g_Blo + nc * 32 * BS);
            for (int i = tid; i < 1056; i += 256) {
                cp16(smu + BHI_OFF + ns * BSTAGE + i * 16, sH + i * 16);
                cp16(smu + BLO_OFF + ns * BSTAGE + i * 16, sL + i * 16);
            }
            cp_commit();
            cp_wait<1>();
        } else {
            cp_wait<0>();
        }
        __syncthreads();

#pragma unroll
        for (int h = 0; h < 2; h++) {
            const int k0 = chunk * 32 + h * 16;
            const int seg = k0 >> 7, kk = k0 & 127;
            const unsigned acol = kk + ((lane >> 4) << 3);
            unsigned ahi[4], alo[4];
            {
                unsigned aoff = (((w << 4) + (lane & 15) + seg) * ES + acol) * 2;
                ldm_x4(ahi, smu + EHI_OFF + aoff);
                ldm_x4(alo, smu + ELO_OFF + aoff);
            }
            unsigned axhi[4], axlo[4];
            if (extra) {
                unsigned ao2 = ((128 + (lane & 15) + seg) * ES + acol) * 2;
                ldm_x4(axhi, smu + EHI_OFF + ao2);
                ldm_x4(axlo, smu + ELO_OFF + ao2);
            }
            const unsigned boff = ((h << 4) + (lane & 15)) * (BS * 2)
                                + ((lane >> 4) << 3) * 2 + stage * BSTAGE;
#pragma unroll
            for (int ng = 0; ng < 16; ng++) {
                unsigned bh[4], bl[4];
                ldm_x4t(bh, smu + BHI_OFF + boff + ng * 32);
                ldm_x4t(bl, smu + BLO_OFF + boff + ng * 32);
                mma16816(cm[ng][0], ahi, bh);
                mma16816(cm[ng][1], ahi, bh + 2);
                mma16816(cm[ng][0], ahi, bl);
                mma16816(cm[ng][1], ahi, bl + 2);
                mma16816(cm[ng][0], alo, bh);
                mma16816(cm[ng][1], alo, bh + 2);
                if (extra && (ng >> 1) == w) {
                    float* e0 = cx[ng & 1][0];
                    float* e1 = cx[ng & 1][1];
                    mma16816(e0, axhi, bh);
                    mma16816(e1, axhi, bh + 2);
                    mma16816(e0, axhi, bl);
                    mma16816(e1, axhi, bl + 2);
                    mma16816(e0, axlo, bh);
                    mma16816(e1, axlo, bh + 2);
                }
            }
        }
        __syncthreads();
    }

    // ---- fused max-pool epilogue ----
#pragma unroll
    for (int ng = 0; ng < 16; ng++)
#pragma unroll
        for (int s = 0; s < 2; s++) {
            float m0 = fmaxf(cm[ng][s][0], cm[ng][s][2]);
            float m1 = fmaxf(cm[ng][s][1], cm[ng][s][3]);
#pragma unroll
            for (int off = 4; off < 32; off <<= 1) {
                m0 = fmaxf(m0, __shfl_xor_sync(0xffffffffu, m0, off));
                m1 = fmaxf(m1, __shfl_xor_sync(0xffffffffu, m1, off));
            }
            if (lane < 4) {
                const int col = ng * 16 + s * 8 + lane * 2;
                wmax[w * 256 + col]     = m0;
                wmax[w * 256 + col + 1] = m1;
            }
        }
    if (extra) {
        const int q = lane >> 2;      // rows 256+q / 264+q; only q<2 valid
#pragma unroll
        for (int g2 = 0; g2 < 2; g2++)
#pragma unroll
            for (int s = 0; s < 2; s++) {
                float m0 = (q < 2) ? cx[g2][s][0] : NEG;
                float m1 = (q < 2) ? cx[g2][s][1] : NEG;
#pragma unroll
                for (int off = 4; off < 32; off <<= 1) {
                    m0 = fmaxf(m0, __shfl_xor_sync(0xffffffffu, m0, off));
                    m1 = fmaxf(m1, __shfl_xor_sync(0xffffffffu, m1, off));
                }
                if (lane < 4) {
                    const int col = (w * 2 + g2) * 16 + s * 8 + lane * 2;
                    wmax[8 * 256 + col]     = m0;
                    wmax[8 * 256 + col + 1] = m1;
                }
            }
    }
    __syncthreads();
    float m = wmax[tid];
#pragma unroll
    for (int r = 1; r < 9; r++) m = fmaxf(m, wmax[r * 256 + tid]);
    const unsigned bits = __float_as_uint(m);
    const unsigned key = (bits & 0x80000000u) ? ~bits : (bits | 0x80000000u);
    atomicMax(&g_featmax[sample * 256 + tid], key);
}

// ---------------------------------------------------------------------------
// Kernel 2: gi = feat @ w_ih^T + b_ih for both directions.
// feat decoded from g_featmax: tanh(conv_b + max).
// ---------------------------------------------------------------------------
__global__ void __launch_bounds__(256) gi_kernel(
    const float* __restrict__ w_ih_f, const float* __restrict__ w_ih_b,
    const float* __restrict__ b_ih_f, const float* __restrict__ b_ih_b,
    const float* __restrict__ conv_b)
{
    __shared__ float As[BATCH * OC];
    const int tid = threadIdx.x;
    const int dir = blockIdx.x >> 6;
    const int n   = blockIdx.x & 63;

    for (int i = tid; i < BATCH * OC; i += 256) {
        const unsigned key = g_featmax[(n * BATCH + (i >> 8)) * 256 + (i & 255)];
        const unsigned bits = (key & 0x80000000u) ? (key & 0x7fffffffu) : ~key;
        As[i] = tanhf(conv_b[i & 255] + __uint_as_float(bits));
    }

    const float* W  = dir ? w_ih_b : w_ih_f;
    const float* bi = dir ? b_ih_b : b_ih_f;
    const float* w0 = W + (tid      ) * OC;
    const float* w1 = W + (tid + 256) * OC;
    const float* w2 = W + (tid + 512) * OC;

    float acc0[32], acc1[32], acc2[32];
#pragma unroll
    for (int bb = 0; bb < 32; bb++) { acc0[bb] = 0.f; acc1[bb] = 0.f; acc2[bb] = 0.f; }
    __syncthreads();

    for (int k4 = 0; k4 < OC / 4; k4++) {
        const float4 v0 = *(const float4*)(w0 + k4 * 4);
        const float4 v1 = *(const float4*)(w1 + k4 * 4);
        const float4 v2 = *(const float4*)(w2 + k4 * 4);
#pragma unroll
        for (int bb = 0; bb < 32; bb++) {
            const float4 a = *(const float4*)&As[bb * OC + k4 * 4];
            acc0[bb] += v0.x * a.x + v0.y * a.y + v0.z * a.z + v0.w * a.w;
            acc1[bb] += v1.x * a.x + v1.y * a.y + v1.z * a.z + v1.w * a.w;
            acc2[bb] += v2.x * a.x + v2.y * a.y + v2.z * a.z + v2.w * a.w;
        }
    }
    const float bi0 = bi[tid], bi1 = bi[tid + 256], bi2 = bi[tid + 512];
    float* go = g_gi + (size_t)((dir * N_NOTES + n) * BATCH) * 768;
#pragma unroll 4
    for (int bb = 0; bb < 32; bb++) {
        go[bb * 768 +       tid] = acc0[bb] + bi0;
        go[bb * 768 + 256 + tid] = acc1[bb] + bi1;
        go[bb * 768 + 512 + tid] = acc2[bb] + bi2;
    }
}

// ---------------------------------------------------------------------------
// Kernel 3: GRU recurrence. CTA = (dir, b) -> 64 independent chains.
// ---------------------------------------------------------------------------
__global__ void __launch_bounds__(256) gru_kernel(
    const float* __restrict__ w_hh_f, const float* __restrict__ w_hh_b,
    const float* __restrict__ b_hh_f, const float* __restrict__ b_hh_b,
    const float* __restrict__ hidden_state,
    float* __restrict__ out)
{
    __shared__ float h[HID];
    const int i   = threadIdx.x;
    const int dir = blockIdx.x >> 5;
    const int b   = blockIdx.x & 31;

    const float* whh = dir ? w_hh_b : w_hh_f;
    const float* bhh = dir ? b_hh_b : b_hh_f;

    h[i] = hidden_state[(dir * BATCH + b) * HID + i];
    const float bh0 = bhh[i], bh1 = bhh[i + 256], bh2 = bhh[i + 512];
    const float* w0 = whh + (i      ) * HID;
    const float* w1 = whh + (i + 256) * HID;
    const float* w2 = whh + (i + 512) * HID;
    __syncthreads();

    for (int s = 0; s < N_NOTES; s++) {
        const int n = dir ? (N_NOTES - 1 - s) : s;
        float g0 = bh0, g1 = bh1, g2 = bh2;
#pragma unroll 4
        for (int k4 = 0; k4 < HID / 4; k4++) {
            const float4 hv = *(const float4*)&h[k4 * 4];
            const float4 a = *(const float4*)(w0 + k4 * 4);
            const float4 c = *(const float4*)(w1 + k4 * 4);
            const float4 e = *(const float4*)(w2 + k4 * 4);
            g0 += a.x * hv.x + a.y * hv.y + a.z * hv.z + a.w * hv.w;
            g1 += c.x * hv.x + c.y * hv.y + c.z * hv.z + c.w * hv.w;
            g2 += e.x * hv.x + e.y * hv.y + e.z * hv.z + e.w * hv.w;
        }
        const float* gp = g_gi + (size_t)((dir * N_NOTES + n) * BATCH + b) * 768;
        const float r  = 1.0f / (1.0f + expf(-(gp[i]       + g0)));
        const float z  = 1.0f / (1.0f + expf(-(gp[i + 256] + g1)));
        const float nn = tanhf(gp[i + 512] + r * g2);
        const float hn = (1.0f - z) * nn + z * h[i];
        __syncthreads();
        h[i] = hn;
        __syncthreads();
        out[(size_t)(n * BATCH + b) * 512 + dir * HID + i] = hn;
    }
}

// ---------------------------------------------------------------------------
// Kernel 4a: transpose W_note -> g_WT[e][d]
// ---------------------------------------------------------------------------
__global__ void __launch_bounds__(256) wnote_transpose_kernel(const float* __restrict__ W)
{
    const int e = blockIdx.x;
    for (int d = threadIdx.x; d < 512; d += 256)
        g_WT[e * 512 + d] = W[d * 512 + e];
}

// ---------------------------------------------------------------------------
// Kernel 4b: additive attention scores
// ---------------------------------------------------------------------------
__global__ void __launch_bounds__(256) attn_kernel(
    const float* __restrict__ out_note,
    const float* __restrict__ bias_note,
    const float* __restrict__ proj_note)
{
    extern __shared__ float As[];               // 32 x 512
    __shared__ float wred[8][32];
    const int tid = threadIdx.x;
    const int n = blockIdx.x;

    const float* src = out_note + (size_t)n * BATCH * 512;
    for (int i = tid; i < (BATCH * 512) / 4; i += 256)
        ((float4*)As)[i] = ((const float4*)src)[i];

    float attnacc[32];
#pragma unroll
    for (int bb = 0; bb < 32; bb++) attnacc[bb] = 0.0f;
    __syncthreads();

    for (int ee = 0; ee < 2; ee++) {
        const int e = ee * 256 + tid;
        const float* w = g_WT + e * 512;
        float acc[32];
#pragma unroll
        for (int bb = 0; bb < 32; bb++) acc[bb] = 0.0f;
        for (int d4 = 0; d4 < 128; d4++) {
            const float4 wv = *(const float4*)(w + d4 * 4);
#pragma unroll
            for (int bb = 0; bb < 32; bb++) {
                const float4 a = *(const float4*)&As[bb * 512 + d4 * 4];
                acc[bb] += wv.x * a.x + wv.y * a.y + wv.z * a.z + wv.w * a.w;
            }
        }
        const float be = bias_note[e], pe = proj_note[e];
#pragma unroll
        for (int bb = 0; bb < 32; bb++)
            attnacc[bb] += tanhf(acc[bb] + be) * pe;
    }
#pragma unroll
    for (int off = 16; off; off >>= 1)
#pragma unroll
        for (int bb = 0; bb < 32; bb++)
            attnacc[bb] += __shfl_xor_sync(0xffffffffu, attnacc[bb], off);
    const int wid = tid >> 5, lane = tid & 31;
    if (lane == 0)
#pragma unroll
        for (int bb = 0; bb < 32; bb++) wred[wid][bb] = attnacc[bb];
    __syncthreads();
    if (tid < 32) {
        float s = 0.0f;
#pragma unroll
        for (int w = 0; w < 8; w++) s += wred[w][tid];
        g_attn[n * BATCH + tid] = s;
    }
}

// ---------------------------------------------------------------------------
// Kernel 5: softmax over notes, weighted sum, final linear. CTA per b.
// ---------------------------------------------------------------------------
__global__ void __launch_bounds__(256) final_kernel(
    const float* __restrict__ out_note,
    const float* __restrict__ lin_w,
    const float* __restrict__ lin_b,
    float* __restrict__ out)
{
    __shared__ float sa[64];
    __shared__ float vec[512];
    __shared__ float stats[2];
    const int tid = threadIdx.x;
    const int b = blockIdx.x;

    if (tid < 64) sa[tid] = g_attn[tid * BATCH + b];
    __syncthreads();
    if (tid < 32) {
        const float v0 = sa[tid], v1 = sa[tid + 32];
        float m = fmaxf(v0, v1);
#pragma unroll
        for (int o = 16; o; o >>= 1) m = fmaxf(m, __shfl_xor_sync(0xffffffffu, m, o));
        float s = expf(v0 - m) + expf(v1 - m);
#pragma unroll
        for (int o = 16; o; o >>= 1) s += __shfl_xor_sync(0xffffffffu, s, o);
        if (tid == 0) { stats[0] = m; stats[1] = s; }
    }
    __syncthreads();
    if (tid < 64) {
        const float nv = expf(sa[tid] - stats[0]) / stats[1];
        sa[tid] = nv;
        out[OFF_NORM + b * 64 + tid] = nv;
    }
    __syncthreads();
#pragma unroll
    for (int dd = 0; dd < 2; dd++) {
        const int d = dd * 256 + tid;
        float acc = 0.0f;
#pragma unroll 8
        for (int n = 0; n < 64; n++)
            acc += sa[n] * out_note[(size_t)(n * BATCH + b) * 512 + d];
        vec[d] = acc;
        out[OFF_VEC + b * 512 + d] = acc;
    }
    __syncthreads();
    if (tid < 64) {
        const int c = tid >> 5, lane = tid & 31;
        float p = 0.0f;
#pragma unroll 4
        for (int i = lane; i < 512; i += 32) p += lin_w[c * 512 + i] * vec[i];
#pragma unroll
        for (int o = 16; o; o >>= 1) p += __shfl_xor_sync(0xffffffffu, p, o);
        if (lane == 0) out[OFF_FIN + b * 2 + c] = p + lin_b[c];
    }
}

// ---------------------------------------------------------------------------
// Launcher
// ---------------------------------------------------------------------------
extern "C" void kernel_launch(void* const* d_in, const int* in_sizes, int n_in,
                              void* d_out, int out_size)
{
    (void)in_sizes; (void)n_in; (void)out_size;
    const int*   mini_batch = (const int*)d_in[0];
    const float* hidden     = (const float*)d_in[1];
    const float* embed      = (const float*)d_in[2];
    const float* conv_w     = (const float*)d_in[3];
    const float* conv_b     = (const float*)d_in[4];
    const float* w_ih_f     = (const float*)d_in[5];
    const float* w_hh_f     = (const float*)d_in[6];
    const float* b_ih_f     = (const float*)d_in[7];
    const float* b_hh_f     = (const float*)d_in[8];
    const float* w_ih_b     = (const float*)d_in[9];
    const float* w_hh_b     = (const float*)d_in[10];
    const float* b_ih_b     = (const float*)d_in[11];
    const float* b_hh_b     = (const float*)d_in[12];
    const float* W_note     = (const float*)d_in[13];
    const float* bias_note  = (const float*)d_in[14];
    const float* proj_note  = (const float*)d_in[15];
    const float* lin_w      = (const float*)d_in[16];
    const float* lin_b      = (const float*)d_in[17];
    float* out = (float*)d_out;

    cudaFuncSetAttribute(conv_mma_kernel,
                         cudaFuncAttributeMaxDynamicSharedMemorySize, CONV2_SMEM);
    cudaFuncSetAttribute(attn_kernel,
                         cudaFuncAttributeMaxDynamicSharedMemorySize, 65536);

    init_featmax_kernel<<<N_NOTES * BATCH, 256>>>();
    wsplit_kernel<<<384, 256>>>(conv_w);
    conv_mma_kernel<<<N_NOTES * BATCH * 2, 256, CONV2_SMEM>>>(mini_batch, embed);
    wnote_transpose_kernel<<<512, 256>>>(W_note);
    gi_kernel<<<128, 256>>>(w_ih_f, w_ih_b, b_ih_f, b_ih_b, conv_b);
    gru_kernel<<<64, 256>>>(w_hh_f, w_hh_b, b_hh_f, b_hh_b, hidden, out);
    attn_kernel<<<64, 256, 65536>>>(out, bias_note, proj_note);
    final_kernel<<<32, 256>>>(out, lin_w, lin_b, out);
}

// round 7
// speedup vs baseline: 1.8926x; 1.1651x over previous
#include <cuda_runtime.h>
#include <cuda_bf16.h>
#include <math.h>

// ---------------------------------------------------------------------------
// Problem constants
// ---------------------------------------------------------------------------
#define N_NOTES   64
#define N_WORDS   256
#define BATCH     32
#define WDIM      128
#define OC        256
#define HID       256

// Output layout (float32)
#define OFF_NORM 1048576
#define OFF_VEC  1050624
#define OFF_FIN  1067008

// ---------------------------------------------------------------------------
// Scratch (device globals)
// ---------------------------------------------------------------------------
__device__ unsigned int  g_featmax[N_NOTES * BATCH * OC];
__device__ float         g_gi[2 * N_NOTES * BATCH * 3 * HID];
__device__ float         g_WT[512 * 512];
__device__ float         g_attn[N_NOTES * BATCH];
__device__ __nv_bfloat16 g_Bhi[384 * 264];   // W^T split hi  [k][n]
__device__ __nv_bfloat16 g_Blo[384 * 264];   // W^T split lo  [k][n]

// ---------------------------------------------------------------------------
// PTX helpers (mma.sync path only — tcgen05 is NOT supported by this target)
// ---------------------------------------------------------------------------
__device__ __forceinline__ void ldm_x4(unsigned* r, unsigned addr) {
    asm volatile("ldmatrix.sync.aligned.m8n8.x4.shared.b16 {%0,%1,%2,%3},[%4];"
        : "=r"(r[0]), "=r"(r[1]), "=r"(r[2]), "=r"(r[3]) : "r"(addr));
}
__device__ __forceinline__ void ldm_x4t(unsigned* r, unsigned addr) {
    asm volatile("ldmatrix.sync.aligned.m8n8.x4.trans.shared.b16 {%0,%1,%2,%3},[%4];"
        : "=r"(r[0]), "=r"(r[1]), "=r"(r[2]), "=r"(r[3]) : "r"(addr));
}
__device__ __forceinline__ void mma16816(float* c, const unsigned* a, const unsigned* b) {
    asm volatile("mma.sync.aligned.m16n8k16.row.col.f32.bf16.bf16.f32 "
        "{%0,%1,%2,%3},{%4,%5,%6,%7},{%8,%9},{%0,%1,%2,%3};"
        : "+f"(c[0]), "+f"(c[1]), "+f"(c[2]), "+f"(c[3])
        : "r"(a[0]), "r"(a[1]), "r"(a[2]), "r"(a[3]), "r"(b[0]), "r"(b[1]));
}
__device__ __forceinline__ void cp16(unsigned dst, const void* src) {
    asm volatile("cp.async.cg.shared.global [%0],[%1],16;" :: "r"(dst), "l"(src));
}
__device__ __forceinline__ void cp_commit() { asm volatile("cp.async.commit_group;"); }
template<int N> __device__ __forceinline__ void cp_wait() {
    asm volatile("cp.async.wait_group %0;" :: "n"(N));
}
__device__ __forceinline__ unsigned enc_key(float m) {
    unsigned bits = __float_as_uint(m);
    return (bits & 0x80000000u) ? ~bits : (bits | 0x80000000u);
}

// ---------------------------------------------------------------------------
// Kernel 0a: reset featmax keys
// ---------------------------------------------------------------------------
__global__ void init_featmax_kernel() {
    g_featmax[blockIdx.x * 256 + threadIdx.x] = 0u;
}

// ---------------------------------------------------------------------------
// Kernel 0b: split + transpose conv_w[oc][k] -> g_Bhi/g_Blo [k][n=oc]
// ---------------------------------------------------------------------------
__global__ void __launch_bounds__(256) wsplit_kernel(const float* __restrict__ conv_w) {
    const int k = blockIdx.x;          // 0..383
    const int n = threadIdx.x;         // 0..255
    float v = conv_w[n * 384 + k];
    __nv_bfloat16 hi = __float2bfloat16(v);
    __nv_bfloat16 lo = __float2bfloat16(v - __bfloat162float(hi));
    g_Bhi[k * 264 + n] = hi;
    g_Blo[k * 264 + n] = lo;
}

// ---------------------------------------------------------------------------
// Kernel 1: conv as bf16x3-split HMMA GEMM, warp tile m64 x n64.
// CTA = (sample, l-half). M=128, N=256, K=384 (x3 split terms).
// ---------------------------------------------------------------------------
#define ES      136        // E row stride (halfs), 272B rows
#define EROWS   132
#define BS      264        // B row stride (halfs), 528B rows
#define BSTAGE  16896      // 32 k-rows * 264 halfs * 2B
#define EHI_OFF 0
#define ELO_OFF 35904
#define BHI_OFF 71808      // 2 stages
#define BLO_OFF 105600     // 2 stages
#define WMAX_OFF 139392    // 2 x 256 floats
#define TOK_OFF  141440    // 132 ints
#define CONV_SMEM 142336

__global__ void __launch_bounds__(256, 1) conv_mma_kernel(
    const int*   __restrict__ mini_batch,   // [64][256][32]
    const float* __restrict__ embed)        // [50000][128]
{
    extern __shared__ char sm[];
    const unsigned smu = (unsigned)__cvta_generic_to_shared(sm);
    const int tid = threadIdx.x, lane = tid & 31, w = tid >> 5;
    const int mg  = w >> 2;        // 0..1  (m group of 64 rows)
    const int ng4 = w & 3;         // 0..3  (n group of 64 cols)
    const int sample = blockIdx.x >> 1;
    const int half   = blockIdx.x & 1;
    const int l0     = half << 7;
    const int n = sample >> 5, b = sample & 31;

    int* tok = (int*)(sm + TOK_OFF);

    // prefetch B chunks 0,1 (hi & lo)
    for (int i = tid; i < 1056; i += 256) {
        cp16(smu + BHI_OFF + i * 16, (const char*)g_Bhi + i * 16);
        cp16(smu + BLO_OFF + i * 16, (const char*)g_Blo + i * 16);
    }
    cp_commit();
    for (int i = tid; i < 1056; i += 256) {
        cp16(smu + BHI_OFF + BSTAGE + i * 16, (const char*)(g_Bhi + 32 * BS) + i * 16);
        cp16(smu + BLO_OFF + BSTAGE + i * 16, (const char*)(g_Blo + 32 * BS) + i * 16);
    }
    cp_commit();

    if (tid < EROWS) {
        const int word = l0 + tid - 2;
        tok[tid] = (word >= 0 && word < N_WORDS)
                 ? mini_batch[(n * N_WORDS + word) * BATCH + b] : -1;
    }
    __syncthreads();

    // ---- build E hi/lo: E[row][dim], bf16 split of gathered embeddings ----
    for (int i = tid; i < EROWS * 32; i += 256) {
        const int row = i >> 5, q = i & 31;
        const int t = tok[row];
        float4 v;
        if (t >= 0) v = *(const float4*)(embed + (size_t)t * WDIM + q * 4);
        else        v = make_float4(0.f, 0.f, 0.f, 0.f);
        __nv_bfloat16 h0 = __float2bfloat16(v.x), h1 = __float2bfloat16(v.y);
        __nv_bfloat16 h2 = __float2bfloat16(v.z), h3 = __float2bfloat16(v.w);
        uint2 hp, lp;
        {
            __nv_bfloat162 a = __halves2bfloat162(h0, h1);
            __nv_bfloat162 c = __halves2bfloat162(h2, h3);
            hp = make_uint2(*(unsigned*)&a, *(unsigned*)&c);
        }
        {
            __nv_bfloat162 a = __halves2bfloat162(
                __float2bfloat16(v.x - __bfloat162float(h0)),
                __float2bfloat16(v.y - __bfloat162float(h1)));
            __nv_bfloat162 c = __halves2bfloat162(
                __float2bfloat16(v.z - __bfloat162float(h2)),
                __float2bfloat16(v.w - __bfloat162float(h3)));
            lp = make_uint2(*(unsigned*)&a, *(unsigned*)&c);
        }
        const unsigned off = (unsigned)(row * ES + q * 4) * 2;
        *(uint2*)(sm + EHI_OFF + off) = hp;
        *(uint2*)(sm + ELO_OFF + off) = lp;
    }

    float cm[4][8][4];
#pragma unroll
    for (int i = 0; i < 4; i++)
#pragma unroll
        for (int j = 0; j < 8; j++)
#pragma unroll
            for (int r = 0; r < 4; r++) cm[i][j][r] = 0.0f;
    __syncthreads();

    // ---- main loop: 12 k-chunks of 32 ----
    for (int c = 0; c < 12; c++) {
        const int stage = c & 1;
        if (c < 11) cp_wait<1>(); else cp_wait<0>();
        __syncthreads();

#pragma unroll
        for (int h = 0; h < 2; h++) {
            const int k0 = c * 32 + h * 16;
            const int seg = k0 >> 7, kk = k0 & 127;
            const unsigned acol = kk + ((lane >> 4) << 3);
            unsigned ahi[4][4], alo[4][4];
#pragma unroll
            for (int mt = 0; mt < 4; mt++) {
                const unsigned aoff =
                    ((mg * 64 + mt * 16 + (lane & 15) + seg) * ES + acol) * 2;
                ldm_x4(ahi[mt], smu + EHI_OFF + aoff);
                ldm_x4(alo[mt], smu + ELO_OFF + aoff);
            }
            const unsigned brow = (h << 4) + (lane & 15);
#pragma unroll
            for (int nn = 0; nn < 4; nn++) {
                const unsigned bcol = ng4 * 64 + nn * 16 + ((lane >> 4) << 3);
                const unsigned boff = stage * BSTAGE + brow * (BS * 2) + bcol * 2;
                unsigned bh[4], bl[4];
                ldm_x4t(bh, smu + BHI_OFF + boff);
                ldm_x4t(bl, smu + BLO_OFF + boff);
#pragma unroll
                for (int mt = 0; mt < 4; mt++) {
                    mma16816(cm[mt][nn * 2],     ahi[mt], bh);
                    mma16816(cm[mt][nn * 2 + 1], ahi[mt], bh + 2);
                    mma16816(cm[mt][nn * 2],     ahi[mt], bl);
                    mma16816(cm[mt][nn * 2 + 1], ahi[mt], bl + 2);
                    mma16816(cm[mt][nn * 2],     alo[mt], bh);
                    mma16816(cm[mt][nn * 2 + 1], alo[mt], bh + 2);
                }
            }
        }
        __syncthreads();
        if (c + 2 < 12) {
            const char* sH = (const char*)(g_Bhi + (c + 2) * 32 * BS);
            const char* sL = (const char*)(g_Blo + (c + 2) * 32 * BS);
            for (int i = tid; i < 1056; i += 256) {
                cp16(smu + BHI_OFF + stage * BSTAGE + i * 16, sH + i * 16);
                cp16(smu + BLO_OFF + stage * BSTAGE + i * 16, sL + i * 16);
            }
            cp_commit();
        }
    }

    // ---- fused max-pool over M (=l) per column ----
    float* wmax = (float*)(sm + WMAX_OFF);
#pragma unroll
    for (int t = 0; t < 8; t++) {
        float m0 = -1e30f, m1 = -1e30f;
#pragma unroll
        for (int mt = 0; mt < 4; mt++) {
            m0 = fmaxf(m0, fmaxf(cm[mt][t][0], cm[mt][t][2]));
            m1 = fmaxf(m1, fmaxf(cm[mt][t][1], cm[mt][t][3]));
        }
#pragma unroll
        for (int off = 4; off < 32; off <<= 1) {
            m0 = fmaxf(m0, __shfl_xor_sync(0xffffffffu, m0, off));
            m1 = fmaxf(m1, __shfl_xor_sync(0xffffffffu, m1, off));
        }
        if (lane < 4) {
            const int col = ng4 * 64 + (t >> 1) * 16 + (t & 1) * 8 + (lane & 3) * 2;
            wmax[mg * 256 + col]     = m0;
            wmax[mg * 256 + col + 1] = m1;
        }
    }
    __syncthreads();
    {
        const float m = fmaxf(wmax[tid], wmax[256 + tid]);
        atomicMax(&g_featmax[sample * 256 + tid], enc_key(m));
    }
}

// ---------------------------------------------------------------------------
// Kernel 1b: conv tail rows l=256,257 (exact fp32). CTA per note n.
// ---------------------------------------------------------------------------
__global__ void __launch_bounds__(256) conv_tail_kernel(
    const int*   __restrict__ mini_batch,
    const float* __restrict__ embed,
    const float* __restrict__ conv_w)
{
    __shared__ float e[2][32][128];          // words 254,255 for all b
    const int n = blockIdx.x, tid = threadIdx.x;
    for (int i = tid; i < 2 * 32 * 32; i += 256) {
        const int ws = i >> 10, b = (i >> 5) & 31, q = i & 31;
        const int t = mini_batch[(n * N_WORDS + 254 + ws) * BATCH + b];
        *(float4*)&e[ws][b][q * 4] = *(const float4*)(embed + (size_t)t * WDIM + q * 4);
    }
    __syncthreads();
    const float* W = conv_w + tid * 384;
#pragma unroll 1
    for (int bg = 0; bg < 4; bg++) {
        float z6[8], z7[8];
#pragma unroll
        for (int i = 0; i < 8; i++) { z6[i] = 0.f; z7[i] = 0.f; }
#pragma unroll 4
        for (int d4 = 0; d4 < 32; d4++) {
            const float4 w0 = *(const float4*)(W + d4 * 4);
            const float4 w1 = *(const float4*)(W + 128 + d4 * 4);
#pragma unroll
            for (int bb = 0; bb < 8; bb++) {
                const int b = bg * 8 + bb;
                const float4 ea = *(const float4*)&e[0][b][d4 * 4];
                const float4 eb = *(const float4*)&e[1][b][d4 * 4];
                z6[bb] += w0.x * ea.x + w0.y * ea.y + w0.z * ea.z + w0.w * ea.w
                        + w1.x * eb.x + w1.y * eb.y + w1.z * eb.z + w1.w * eb.w;
                z7[bb] += w0.x * eb.x + w0.y * eb.y + w0.z * eb.z + w0.w * eb.w;
            }
        }
#pragma unroll
        for (int bb = 0; bb < 8; bb++) {
            const int b = bg * 8 + bb;
            atomicMax(&g_featmax[(n * BATCH + b) * 256 + tid],
                      enc_key(fmaxf(z6[bb], z7[bb])));
        }
    }
}

// ---------------------------------------------------------------------------
// Kernel 2: gi = feat @ w_ih^T + b_ih (feat decoded: tanh(conv_b + max))
// ---------------------------------------------------------------------------
__global__ void __launch_bounds__(256) gi_kernel(
    const float* __restrict__ w_ih_f, const float* __restrict__ w_ih_b,
    const float* __restrict__ b_ih_f, const float* __restrict__ b_ih_b,
    const float* __restrict__ conv_b)
{
    __shared__ float As[BATCH * OC];
    const int tid = threadIdx.x;
    const int dir = blockIdx.x >> 6;
    const int n   = blockIdx.x & 63;

    for (int i = tid; i < BATCH * OC; i += 256) {
        const unsigned key = g_featmax[(n * BATCH + (i >> 8)) * 256 + (i & 255)];
        const unsigned bits = (key & 0x80000000u) ? (key & 0x7fffffffu) : ~key;
        As[i] = tanhf(conv_b[i & 255] + __uint_as_float(bits));
    }

    const float* W  = dir ? w_ih_b : w_ih_f;
    const float* bi = dir ? b_ih_b : b_ih_f;
    const float* w0 = W + (tid      ) * OC;
    const float* w1 = W + (tid + 256) * OC;
    const float* w2 = W + (tid + 512) * OC;

    float acc0[32], acc1[32], acc2[32];
#pragma unroll
    for (int bb = 0; bb < 32; bb++) { acc0[bb] = 0.f; acc1[bb] = 0.f; acc2[bb] = 0.f; }
    __syncthreads();

    for (int k4 = 0; k4 < OC / 4; k4++) {
        const float4 v0 = *(const float4*)(w0 + k4 * 4);
        const float4 v1 = *(const float4*)(w1 + k4 * 4);
        const float4 v2 = *(const float4*)(w2 + k4 * 4);
#pragma unroll
        for (int bb = 0; bb < 32; bb++) {
            const float4 a = *(const float4*)&As[bb * OC + k4 * 4];
            acc0[bb] += v0.x * a.x + v0.y * a.y + v0.z * a.z + v0.w * a.w;
            acc1[bb] += v1.x * a.x + v1.y * a.y + v1.z * a.z + v1.w * a.w;
            acc2[bb] += v2.x * a.x + v2.y * a.y + v2.z * a.z + v2.w * a.w;
        }
    }
    const float bi0 = bi[tid], bi1 = bi[tid + 256], bi2 = bi[tid + 512];
    float* go = g_gi + (size_t)((dir * N_NOTES + n) * BATCH) * 768;
#pragma unroll 4
    for (int bb = 0; bb < 32; bb++) {
        go[bb * 768 +       tid] = acc0[bb] + bi0;
        go[bb * 768 + 256 + tid] = acc1[bb] + bi1;
        go[bb * 768 + 512 + tid] = acc2[bb] + bi2;
    }
}

// ---------------------------------------------------------------------------
// Kernel 3: GRU recurrence. CTA = (dir, b).
// ---------------------------------------------------------------------------
__global__ void __launch_bounds__(256) gru_kernel(
    const float* __restrict__ w_hh_f, const float* __restrict__ w_hh_b,
    const float* __restrict__ b_hh_f, const float* __restrict__ b_hh_b,
    const float* __restrict__ hidden_state,
    float* __restrict__ out)
{
    __shared__ float h[HID];
    const int i   = threadIdx.x;
    const int dir = blockIdx.x >> 5;
    const int b   = blockIdx.x & 31;

    const float* whh = dir ? w_hh_b : w_hh_f;
    const float* bhh = dir ? b_hh_b : b_hh_f;

    h[i] = hidden_state[(dir * BATCH + b) * HID + i];
    const float bh0 = bhh[i], bh1 = bhh[i + 256], bh2 = bhh[i + 512];
    const float* w0 = whh + (i      ) * HID;
    const float* w1 = whh + (i + 256) * HID;
    const float* w2 = whh + (i + 512) * HID;
    __syncthreads();

    for (int s = 0; s < N_NOTES; s++) {
        const int n = dir ? (N_NOTES - 1 - s) : s;
        float g0 = bh0, g1 = bh1, g2 = bh2;
#pragma unroll 4
        for (int k4 = 0; k4 < HID / 4; k4++) {
            const float4 hv = *(const float4*)&h[k4 * 4];
            const float4 a = *(const float4*)(w0 + k4 * 4);
            const float4 c = *(const float4*)(w1 + k4 * 4);
            const float4 e = *(const float4*)(w2 + k4 * 4);
            g0 += a.x * hv.x + a.y * hv.y + a.z * hv.z + a.w * hv.w;
            g1 += c.x * hv.x + c.y * hv.y + c.z * hv.z + c.w * hv.w;
            g2 += e.x * hv.x + e.y * hv.y + e.z * hv.z + e.w * hv.w;
        }
        const float* gp = g_gi + (size_t)((dir * N_NOTES + n) * BATCH + b) * 768;
        const float r  = 1.0f / (1.0f + expf(-(gp[i]       + g0)));
        const float z  = 1.0f / (1.0f + expf(-(gp[i + 256] + g1)));
        const float nn = tanhf(gp[i + 512] + r * g2);
        const float hn = (1.0f - z) * nn + z * h[i];
        __syncthreads();
        h[i] = hn;
        __syncthreads();
        out[(size_t)(n * BATCH + b) * 512 + dir * HID + i] = hn;
    }
}

// ---------------------------------------------------------------------------
// Kernel 4a: transpose W_note -> g_WT[e][d]
// ---------------------------------------------------------------------------
__global__ void __launch_bounds__(256) wnote_transpose_kernel(const float* __restrict__ W)
{
    const int e = blockIdx.x;
    for (int d = threadIdx.x; d < 512; d += 256)
        g_WT[e * 512 + d] = W[d * 512 + e];
}

// ---------------------------------------------------------------------------
// Kernel 4b: additive attention scores
// ---------------------------------------------------------------------------
__global__ void __launch_bounds__(256) attn_kernel(
    const float* __restrict__ out_note,
    const float* __restrict__ bias_note,
    const float* __restrict__ proj_note)
{
    extern __shared__ float As[];
    __shared__ float wred[8][32];
    const int tid = threadIdx.x;
    const int n = blockIdx.x;

    const float* src = out_note + (size_t)n * BATCH * 512;
    for (int i = tid; i < (BATCH * 512) / 4; i += 256)
        ((float4*)As)[i] = ((const float4*)src)[i];

    float attnacc[32];
#pragma unroll
    for (int bb = 0; bb < 32; bb++) attnacc[bb] = 0.0f;
    __syncthreads();

    for (int ee = 0; ee < 2; ee++) {
        const int e = ee * 256 + tid;
        const float* w = g_WT + e * 512;
        float acc[32];
#pragma unroll
        for (int bb = 0; bb < 32; bb++) acc[bb] = 0.0f;
        for (int d4 = 0; d4 < 128; d4++) {
            const float4 wv = *(const float4*)(w + d4 * 4);
#pragma unroll
            for (int bb = 0; bb < 32; bb++) {
                const float4 a = *(const float4*)&As[bb * 512 + d4 * 4];
                acc[bb] += wv.x * a.x + wv.y * a.y + wv.z * a.z + wv.w * a.w;
            }
        }
        const float be = bias_note[e], pe = proj_note[e];
#pragma unroll
        for (int bb = 0; bb < 32; bb++)
            attnacc[bb] += tanhf(acc[bb] + be) * pe;
    }
#pragma unroll
    for (int off = 16; off; off >>= 1)
#pragma unroll
        for (int bb = 0; bb < 32; bb++)
            attnacc[bb] += __shfl_xor_sync(0xffffffffu, attnacc[bb], off);
    const int wid = tid >> 5, lane = tid & 31;
    if (lane == 0)
#pragma unroll
        for (int bb = 0; bb < 32; bb++) wred[wid][bb] = attnacc[bb];
    __syncthreads();
    if (tid < 32) {
        float s = 0.0f;
#pragma unroll
        for (int w = 0; w < 8; w++) s += wred[w][tid];
        g_attn[n * BATCH + tid] = s;
    }
}

// ---------------------------------------------------------------------------
// Kernel 5: softmax + weighted sum + final linear. CTA per b.
// ---------------------------------------------------------------------------
__global__ void __launch_bounds__(256) final_kernel(
    const float* __restrict__ out_note,
    const float* __restrict__ lin_w,
    const float* __restrict__ lin_b,
    float* __restrict__ out)
{
    __shared__ float sa[64];
    __shared__ float vec[512];
    __shared__ float stats[2];
    const int tid = threadIdx.x;
    const int b = blockIdx.x;

    if (tid < 64) sa[tid] = g_attn[tid * BATCH + b];
    __syncthreads();
    if (tid < 32) {
        const float v0 = sa[tid], v1 = sa[tid + 32];
        float m = fmaxf(v0, v1);
#pragma unroll
        for (int o = 16; o; o >>= 1) m = fmaxf(m, __shfl_xor_sync(0xffffffffu, m, o));
        float s = expf(v0 - m) + expf(v1 - m);
#pragma unroll
        for (int o = 16; o; o >>= 1) s += __shfl_xor_sync(0xffffffffu, s, o);
        if (tid == 0) { stats[0] = m; stats[1] = s; }
    }
    __syncthreads();
    if (tid < 64) {
        const float nv = expf(sa[tid] - stats[0]) / stats[1];
        sa[tid] = nv;
        out[OFF_NORM + b * 64 + tid] = nv;
    }
    __syncthreads();
#pragma unroll
    for (int dd = 0; dd < 2; dd++) {
        const int d = dd * 256 + tid;
        float acc = 0.0f;
#pragma unroll 8
        for (int n = 0; n < 64; n++)
            acc += sa[n] * out_note[(size_t)(n * BATCH + b) * 512 + d];
        vec[d] = acc;
        out[OFF_VEC + b * 512 + d] = acc;
    }
    __syncthreads();
    if (tid < 64) {
        const int c = tid >> 5, lane = tid & 31;
        float p = 0.0f;
#pragma unroll 4
        for (int i = lane; i < 512; i += 32) p += lin_w[c * 512 + i] * vec[i];
#pragma unroll
        for (int o = 16; o; o >>= 1) p += __shfl_xor_sync(0xffffffffu, p, o);
        if (lane == 0) out[OFF_FIN + b * 2 + c] = p + lin_b[c];
    }
}

// ---------------------------------------------------------------------------
// Launcher
// ---------------------------------------------------------------------------
extern "C" void kernel_launch(void* const* d_in, const int* in_sizes, int n_in,
                              void* d_out, int out_size)
{
    (void)in_sizes; (void)n_in; (void)out_size;
    const int*   mini_batch = (const int*)d_in[0];
    const float* hidden     = (const float*)d_in[1];
    const float* embed      = (const float*)d_in[2];
    const float* conv_w     = (const float*)d_in[3];
    const float* conv_b     = (const float*)d_in[4];
    const float* w_ih_f     = (const float*)d_in[5];
    const float* w_hh_f     = (const float*)d_in[6];
    const float* b_ih_f     = (const float*)d_in[7];
    const float* b_hh_f     = (const float*)d_in[8];
    const float* w_ih_b     = (const float*)d_in[9];
    const float* w_hh_b     = (const float*)d_in[10];
    const float* b_ih_b     = (const float*)d_in[11];
    const float* b_hh_b     = (const float*)d_in[12];
    const float* W_note     = (const float*)d_in[13];
    const float* bias_note  = (const float*)d_in[14];
    const float* proj_note  = (const float*)d_in[15];
    const float* lin_w      = (const float*)d_in[16];
    const float* lin_b      = (const float*)d_in[17];
    float* out = (float*)d_out;

    cudaFuncSetAttribute(conv_mma_kernel,
                         cudaFuncAttributeMaxDynamicSharedMemorySize, CONV_SMEM);
    cudaFuncSetAttribute(attn_kernel,
                         cudaFuncAttributeMaxDynamicSharedMemorySize, 65536);

    init_featmax_kernel<<<N_NOTES * BATCH, 256>>>();
    wsplit_kernel<<<384, 256>>>(conv_w);
    conv_mma_kernel<<<N_NOTES * BATCH * 2, 256, CONV_SMEM>>>(mini_batch, embed);
    conv_tail_kernel<<<N_NOTES, 256>>>(mini_batch, embed, conv_w);
    wnote_transpose_kernel<<<512, 256>>>(W_note);
    gi_kernel<<<128, 256>>>(w_ih_f, w_ih_b, b_ih_f, b_ih_b, conv_b);
    gru_kernel<<<64, 256>>>(w_hh_f, w_hh_b, b_hh_f, b_hh_b, hidden, out);
    attn_kernel<<<64, 256, 65536>>>(out, bias_note, proj_note);
    final_kernel<<<32, 256>>>(out, lin_w, lin_b, out);
}

// round 8
// speedup vs baseline: 2.1338x; 1.1274x over previous
#include <cuda_runtime.h>
#include <cuda_fp16.h>
#include <math.h>

// ---------------------------------------------------------------------------
// Problem constants
// ---------------------------------------------------------------------------
#define N_NOTES   64
#define N_WORDS   256
#define BATCH     32
#define WDIM      128
#define OC        256
#define HID       256

// Output layout (float32)
#define OFF_NORM 1048576
#define OFF_VEC  1050624
#define OFF_FIN  1067008

// ---------------------------------------------------------------------------
// Scratch (device globals)
// ---------------------------------------------------------------------------
__device__ unsigned int g_featmax[N_NOTES * BATCH * OC];
__device__ float        g_gi[2 * N_NOTES * BATCH * 3 * HID];
__device__ float        g_WT[512 * 512];
__device__ float        g_attn[N_NOTES * BATCH];
__device__ __half       g_Bhi[384 * 264];   // W^T fp16 hi       [k][n]
__device__ __half       g_Blo[384 * 264];   // W^T fp16 hi*2^-8  [k][n]

// ---------------------------------------------------------------------------
// PTX helpers (mma.sync path — tcgen05 NOT supported by this ptxas target)
// ---------------------------------------------------------------------------
__device__ __forceinline__ void ldm_x4(unsigned* r, unsigned addr) {
    asm volatile("ldmatrix.sync.aligned.m8n8.x4.shared.b16 {%0,%1,%2,%3},[%4];"
        : "=r"(r[0]), "=r"(r[1]), "=r"(r[2]), "=r"(r[3]) : "r"(addr));
}
__device__ __forceinline__ void ldm_x4t(unsigned* r, unsigned addr) {
    asm volatile("ldmatrix.sync.aligned.m8n8.x4.trans.shared.b16 {%0,%1,%2,%3},[%4];"
        : "=r"(r[0]), "=r"(r[1]), "=r"(r[2]), "=r"(r[3]) : "r"(addr));
}
__device__ __forceinline__ void mma16816(float* c, const unsigned* a, const unsigned* b) {
    asm volatile("mma.sync.aligned.m16n8k16.row.col.f32.f16.f16.f32 "
        "{%0,%1,%2,%3},{%4,%5,%6,%7},{%8,%9},{%0,%1,%2,%3};"
        : "+f"(c[0]), "+f"(c[1]), "+f"(c[2]), "+f"(c[3])
        : "r"(a[0]), "r"(a[1]), "r"(a[2]), "r"(a[3]), "r"(b[0]), "r"(b[1]));
}
__device__ __forceinline__ void cp16(unsigned dst, const void* src) {
    asm volatile("cp.async.cg.shared.global [%0],[%1],16;" :: "r"(dst), "l"(src));
}
__device__ __forceinline__ void cp_commit() { asm volatile("cp.async.commit_group;"); }
template<int N> __device__ __forceinline__ void cp_wait() {
    asm volatile("cp.async.wait_group %0;" :: "n"(N));
}
__device__ __forceinline__ unsigned enc_key(float m) {
    unsigned bits = __float_as_uint(m);
    return (bits & 0x80000000u) ? ~bits : (bits | 0x80000000u);
}

// ---------------------------------------------------------------------------
// Kernel 0a: reset featmax keys
// ---------------------------------------------------------------------------
__global__ void init_featmax_kernel() {
    g_featmax[blockIdx.x * 256 + threadIdx.x] = 0u;
}

// ---------------------------------------------------------------------------
// Kernel 0b: conv_w[oc][k] -> fp16 hi + (hi * 2^-8) images, transposed [k][n]
// ---------------------------------------------------------------------------
__global__ void __launch_bounds__(256) wsplit_kernel(const float* __restrict__ conv_w) {
    const int k = blockIdx.x;          // 0..383
    const int n = threadIdx.x;         // 0..255
    const float v = conv_w[n * 384 + k];
    const __half hi = __float2half(v);
    g_Bhi[k * 264 + n] = hi;
    g_Blo[k * 264 + n] = __float2half(__half2float(hi) * 0.00390625f);  // * 2^-8
}

// ---------------------------------------------------------------------------
// Kernel 1: conv as fp16 2-term HMMA GEMM, 512 threads, warp tile m32 x n64.
// CTA = (sample, l-half). M=128, N=256, K=384.
//   z = ahi*bhi + ((a-ahi)*2^8)*(bhi*2^-8)   (drops ahi*(b-bhi) ~ 2^-12 rel)
// ---------------------------------------------------------------------------
#define ES      136        // E row stride (halfs), 272B rows
#define EROWS   132
#define BS      264        // B row stride (halfs), 528B rows
#define BSTAGE  16896      // 32 k-rows * 264 halfs * 2B
#define EHI_OFF 0
#define ELO_OFF 35904
#define BHI_OFF 71808      // 2 stages
#define BLO_OFF 105600     // 2 stages
#define WMAX_OFF 139392    // 4 x 256 floats
#define TOK_OFF  143488    // 132 ints
#define CONV_SMEM 144064

__global__ void __launch_bounds__(512, 1) conv_mma_kernel(
    const int*   __restrict__ mini_batch,   // [64][256][32]
    const float* __restrict__ embed)        // [50000][128]
{
    extern __shared__ char sm[];
    const unsigned smu = (unsigned)__cvta_generic_to_shared(sm);
    const int tid = threadIdx.x, lane = tid & 31, w = tid >> 5;
    const int mg = w >> 2;         // 0..3  (m block of 32 rows)
    const int ng = w & 3;          // 0..3  (n block of 64 cols)
    const int sample = blockIdx.x >> 1;
    const int half   = blockIdx.x & 1;
    const int l0     = half << 7;
    const int n = sample >> 5, b = sample & 31;

    int* tok = (int*)(sm + TOK_OFF);

    // prefetch B chunks 0,1 (hi & lo)
    for (int i = tid; i < 1056; i += 512) {
        cp16(smu + BHI_OFF + i * 16, (const char*)g_Bhi + i * 16);
        cp16(smu + BLO_OFF + i * 16, (const char*)g_Blo + i * 16);
    }
    cp_commit();
    for (int i = tid; i < 1056; i += 512) {
        cp16(smu + BHI_OFF + BSTAGE + i * 16, (const char*)(g_Bhi + 32 * BS) + i * 16);
        cp16(smu + BLO_OFF + BSTAGE + i * 16, (const char*)(g_Blo + 32 * BS) + i * 16);
    }
    cp_commit();

    if (tid < EROWS) {
        const int word = l0 + tid - 2;
        tok[tid] = (word >= 0 && word < N_WORDS)
                 ? mini_batch[(n * N_WORDS + word) * BATCH + b] : -1;
    }
    __syncthreads();

    // ---- build E hi / lo' ----
    for (int i = tid; i < EROWS * 32; i += 512) {
        const int row = i >> 5, q = i & 31;
        const int t = tok[row];
        float4 v;
        if (t >= 0) v = *(const float4*)(embed + (size_t)t * WDIM + q * 4);
        else        v = make_float4(0.f, 0.f, 0.f, 0.f);
        const __half h0 = __float2half(v.x), h1 = __float2half(v.y);
        const __half h2 = __float2half(v.z), h3 = __float2half(v.w);
        __half2 hp0 = __halves2half2(h0, h1);
        __half2 hp1 = __halves2half2(h2, h3);
        __half2 lp0 = __halves2half2(
            __float2half((v.x - __half2float(h0)) * 256.0f),
            __float2half((v.y - __half2float(h1)) * 256.0f));
        __half2 lp1 = __halves2half2(
            __float2half((v.z - __half2float(h2)) * 256.0f),
            __float2half((v.w - __half2float(h3)) * 256.0f));
        const unsigned off = (unsigned)(row * ES + q * 4) * 2;
        *(uint2*)(sm + EHI_OFF + off) = make_uint2(*(unsigned*)&hp0, *(unsigned*)&hp1);
        *(uint2*)(sm + ELO_OFF + off) = make_uint2(*(unsigned*)&lp0, *(unsigned*)&lp1);
    }

    float cm[2][8][4];
#pragma unroll
    for (int i = 0; i < 2; i++)
#pragma unroll
        for (int j = 0; j < 8; j++)
#pragma unroll
            for (int r = 0; r < 4; r++) cm[i][j][r] = 0.0f;
    __syncthreads();

    // ---- main loop: 12 k-chunks of 32 ----
    for (int c = 0; c < 12; c++) {
        const int stage = c & 1;
        if (c < 11) cp_wait<1>(); else cp_wait<0>();
        __syncthreads();

#pragma unroll
        for (int h = 0; h < 2; h++) {
            const int k0 = c * 32 + h * 16;
            const int seg = k0 >> 7, kk = k0 & 127;
            const unsigned acol = kk + ((lane >> 4) << 3);
            unsigned ahi[2][4], alo[2][4];
#pragma unroll
            for (int mt = 0; mt < 2; mt++) {
                const unsigned aoff =
                    ((mg * 32 + mt * 16 + (lane & 15) + seg) * ES + acol) * 2;
                ldm_x4(ahi[mt], smu + EHI_OFF + aoff);
                ldm_x4(alo[mt], smu + ELO_OFF + aoff);
            }
            const unsigned brow = (h << 4) + (lane & 15);
#pragma unroll
            for (int nn = 0; nn < 4; nn++) {
                const unsigned bcol = ng * 64 + nn * 16 + ((lane >> 4) << 3);
                const unsigned boff = stage * BSTAGE + brow * (BS * 2) + bcol * 2;
                unsigned bh[4], bl[4];
                ldm_x4t(bh, smu + BHI_OFF + boff);
                ldm_x4t(bl, smu + BLO_OFF + boff);
#pragma unroll
                for (int mt = 0; mt < 2; mt++) {
                    mma16816(cm[mt][nn * 2],     ahi[mt], bh);
                    mma16816(cm[mt][nn * 2 + 1], ahi[mt], bh + 2);
                    mma16816(cm[mt][nn * 2],     alo[mt], bl);
                    mma16816(cm[mt][nn * 2 + 1], alo[mt], bl + 2);
                }
            }
        }
        __syncthreads();
        if (c + 2 < 12) {
            const char* sH = (const char*)(g_Bhi + (c + 2) * 32 * BS);
            const char* sL = (const char*)(g_Blo + (c + 2) * 32 * BS);
            for (int i = tid; i < 1056; i += 512) {
                cp16(smu + BHI_OFF + stage * BSTAGE + i * 16, sH + i * 16);
                cp16(smu + BLO_OFF + stage * BSTAGE + i * 16, sL + i * 16);
            }
            cp_commit();
        }
    }

    // ---- fused max-pool over M (=l) per column ----
    float* wmax = (float*)(sm + WMAX_OFF);
#pragma unroll
    for (int t = 0; t < 8; t++) {
        float m0 = fmaxf(fmaxf(cm[0][t][0], cm[0][t][2]),
                         fmaxf(cm[1][t][0], cm[1][t][2]));
        float m1 = fmaxf(fmaxf(cm[0][t][1], cm[0][t][3]),
                         fmaxf(cm[1][t][1], cm[1][t][3]));
#pragma unroll
        for (int off = 4; off < 32; off <<= 1) {
            m0 = fmaxf(m0, __shfl_xor_sync(0xffffffffu, m0, off));
            m1 = fmaxf(m1, __shfl_xor_sync(0xffffffffu, m1, off));
        }
        if (lane < 4) {
            const int col = ng * 64 + (t >> 1) * 16 + (t & 1) * 8 + lane * 2;
            wmax[mg * 256 + col]     = m0;
            wmax[mg * 256 + col + 1] = m1;
        }
    }
    __syncthreads();
    if (tid < 256) {
        const float m = fmaxf(fmaxf(wmax[tid], wmax[256 + tid]),
                              fmaxf(wmax[512 + tid], wmax[768 + tid]));
        atomicMax(&g_featmax[sample * 256 + tid], enc_key(m));
    }
}

// ---------------------------------------------------------------------------
// Kernel 1b: conv tail rows l=256,257 (exact fp32). CTA per note n.
// ---------------------------------------------------------------------------
__global__ void __launch_bounds__(256) conv_tail_kernel(
    const int*   __restrict__ mini_batch,
    const float* __restrict__ embed,
    const float* __restrict__ conv_w)
{
    __shared__ float e[2][32][128];          // words 254,255 for all b
    const int n = blockIdx.x, tid = threadIdx.x;
    for (int i = tid; i < 2 * 32 * 32; i += 256) {
        const int ws = i >> 10, b = (i >> 5) & 31, q = i & 31;
        const int t = mini_batch[(n * N_WORDS + 254 + ws) * BATCH + b];
        *(float4*)&e[ws][b][q * 4] = *(const float4*)(embed + (size_t)t * WDIM + q * 4);
    }
    __syncthreads();
    const float* W = conv_w + tid * 384;
#pragma unroll 1
    for (int bg = 0; bg < 4; bg++) {
        float z6[8], z7[8];
#pragma unroll
        for (int i = 0; i < 8; i++) { z6[i] = 0.f; z7[i] = 0.f; }
#pragma unroll 4
        for (int d4 = 0; d4 < 32; d4++) {
            const float4 w0 = *(const float4*)(W + d4 * 4);
            const float4 w1 = *(const float4*)(W + 128 + d4 * 4);
#pragma unroll
            for (int bb = 0; bb < 8; bb++) {
                const int b = bg * 8 + bb;
                const float4 ea = *(const float4*)&e[0][b][d4 * 4];
                const float4 eb = *(const float4*)&e[1][b][d4 * 4];
                z6[bb] += w0.x * ea.x + w0.y * ea.y + w0.z * ea.z + w0.w * ea.w
                        + w1.x * eb.x + w1.y * eb.y + w1.z * eb.z + w1.w * eb.w;
                z7[bb] += w0.x * eb.x + w0.y * eb.y + w0.z * eb.z + w0.w * eb.w;
            }
        }
#pragma unroll
        for (int bb = 0; bb < 8; bb++) {
            const int b = bg * 8 + bb;
            atomicMax(&g_featmax[(n * BATCH + b) * 256 + tid],
                      enc_key(fmaxf(z6[bb], z7[bb])));
        }
    }
}

// ---------------------------------------------------------------------------
// Kernel 2: gi = feat @ w_ih^T + b_ih (feat decoded: tanh(conv_b + max))
// ---------------------------------------------------------------------------
__global__ void __launch_bounds__(256) gi_kernel(
    const float* __restrict__ w_ih_f, const float* __restrict__ w_ih_b,
    const float* __restrict__ b_ih_f, const float* __restrict__ b_ih_b,
    const float* __restrict__ conv_b)
{
    __shared__ float As[BATCH * OC];
    const int tid = threadIdx.x;
    const int dir = blockIdx.x >> 6;
    const int n   = blockIdx.x & 63;

    for (int i = tid; i < BATCH * OC; i += 256) {
        const unsigned key = g_featmax[(n * BATCH + (i >> 8)) * 256 + (i & 255)];
        const unsigned bits = (key & 0x80000000u) ? (key & 0x7fffffffu) : ~key;
        As[i] = tanhf(conv_b[i & 255] + __uint_as_float(bits));
    }

    const float* W  = dir ? w_ih_b : w_ih_f;
    const float* bi = dir ? b_ih_b : b_ih_f;
    const float* w0 = W + (tid      ) * OC;
    const float* w1 = W + (tid + 256) * OC;
    const float* w2 = W + (tid + 512) * OC;

    float acc0[32], acc1[32], acc2[32];
#pragma unroll
    for (int bb = 0; bb < 32; bb++) { acc0[bb] = 0.f; acc1[bb] = 0.f; acc2[bb] = 0.f; }
    __syncthreads();

    for (int k4 = 0; k4 < OC / 4; k4++) {
        const float4 v0 = *(const float4*)(w0 + k4 * 4);
        const float4 v1 = *(const float4*)(w1 + k4 * 4);
        const float4 v2 = *(const float4*)(w2 + k4 * 4);
#pragma unroll
        for (int bb = 0; bb < 32; bb++) {
            const float4 a = *(const float4*)&As[bb * OC + k4 * 4];
            acc0[bb] += v0.x * a.x + v0.y * a.y + v0.z * a.z + v0.w * a.w;
            acc1[bb] += v1.x * a.x + v1.y * a.y + v1.z * a.z + v1.w * a.w;
            acc2[bb] += v2.x * a.x + v2.y * a.y + v2.z * a.z + v2.w * a.w;
        }
    }
    const float bi0 = bi[tid], bi1 = bi[tid + 256], bi2 = bi[tid + 512];
    float* go = g_gi + (size_t)((dir * N_NOTES + n) * BATCH) * 768;
#pragma unroll 4
    for (int bb = 0; bb < 32; bb++) {
        go[bb * 768 +       tid] = acc0[bb] + bi0;
        go[bb * 768 + 256 + tid] = acc1[bb] + bi1;
        go[bb * 768 + 512 + tid] = acc2[bb] + bi2;
    }
}

// ---------------------------------------------------------------------------
// Kernel 3: GRU recurrence. CTA = (dir, b).
// ---------------------------------------------------------------------------
__global__ void __launch_bounds__(256) gru_kernel(
    const float* __restrict__ w_hh_f, const float* __restrict__ w_hh_b,
    const float* __restrict__ b_hh_f, const float* __restrict__ b_hh_b,
    const float* __restrict__ hidden_state,
    float* __restrict__ out)
{
    __shared__ float h[HID];
    const int i   = threadIdx.x;
    const int dir = blockIdx.x >> 5;
    const int b   = blockIdx.x & 31;

    const float* whh = dir ? w_hh_b : w_hh_f;
    const float* bhh = dir ? b_hh_b : b_hh_f;

    h[i] = hidden_state[(dir * BATCH + b) * HID + i];
    const float bh0 = bhh[i], bh1 = bhh[i + 256], bh2 = bhh[i + 512];
    const float* w0 = whh + (i      ) * HID;
    const float* w1 = whh + (i + 256) * HID;
    const float* w2 = whh + (i + 512) * HID;
    __syncthreads();

    for (int s = 0; s < N_NOTES; s++) {
        const int n = dir ? (N_NOTES - 1 - s) : s;
        float g0 = bh0, g1 = bh1, g2 = bh2;
#pragma unroll 4
        for (int k4 = 0; k4 < HID / 4; k4++) {
            const float4 hv = *(const float4*)&h[k4 * 4];
            const float4 a = *(const float4*)(w0 + k4 * 4);
            const float4 c = *(const float4*)(w1 + k4 * 4);
            const float4 e = *(const float4*)(w2 + k4 * 4);
            g0 += a.x * hv.x + a.y * hv.y + a.z * hv.z + a.w * hv.w;
            g1 += c.x * hv.x + c.y * hv.y + c.z * hv.z + c.w * hv.w;
            g2 += e.x * hv.x + e.y * hv.y + e.z * hv.z + e.w * hv.w;
        }
        const float* gp = g_gi + (size_t)((dir * N_NOTES + n) * BATCH + b) * 768;
        const float r  = 1.0f / (1.0f + expf(-(gp[i]       + g0)));
        const float z  = 1.0f / (1.0f + expf(-(gp[i + 256] + g1)));
        const float nn = tanhf(gp[i + 512] + r * g2);
        const float hn = (1.0f - z) * nn + z * h[i];
        __syncthreads();
        h[i] = hn;
        __syncthreads();
        out[(size_t)(n * BATCH + b) * 512 + dir * HID + i] = hn;
    }
}

// ---------------------------------------------------------------------------
// Kernel 4a: transpose W_note -> g_WT[e][d]
// ---------------------------------------------------------------------------
__global__ void __launch_bounds__(256) wnote_transpose_kernel(const float* __restrict__ W)
{
    const int e = blockIdx.x;
    for (int d = threadIdx.x; d < 512; d += 256)
        g_WT[e * 512 + d] = W[d * 512 + e];
}

// ---------------------------------------------------------------------------
// Kernel 4b: additive attention scores
// ---------------------------------------------------------------------------
__global__ void __launch_bounds__(256) attn_kernel(
    const float* __restrict__ out_note,
    const float* __restrict__ bias_note,
    const float* __restrict__ proj_note)
{
    extern __shared__ float As[];
    __shared__ float wred[8][32];
    const int tid = threadIdx.x;
    const int n = blockIdx.x;

    const float* src = out_note + (size_t)n * BATCH * 512;
    for (int i = tid; i < (BATCH * 512) / 4; i += 256)
        ((float4*)As)[i] = ((const float4*)src)[i];

    float attnacc[32];
#pragma unroll
    for (int bb = 0; bb < 32; bb++) attnacc[bb] = 0.0f;
    __syncthreads();

    for (int ee = 0; ee < 2; ee++) {
        const int e = ee * 256 + tid;
        const float* w = g_WT + e * 512;
        float acc[32];
#pragma unroll
        for (int bb = 0; bb < 32; bb++) acc[bb] = 0.0f;
        for (int d4 = 0; d4 < 128; d4++) {
            const float4 wv = *(const float4*)(w + d4 * 4);
#pragma unroll
            for (int bb = 0; bb < 32; bb++) {
                const float4 a = *(const float4*)&As[bb * 512 + d4 * 4];
                acc[bb] += wv.x * a.x + wv.y * a.y + wv.z * a.z + wv.w * a.w;
            }
        }
        const float be = bias_note[e], pe = proj_note[e];
#pragma unroll
        for (int bb = 0; bb < 32; bb++)
            attnacc[bb] += tanhf(acc[bb] + be) * pe;
    }
#pragma unroll
    for (int off = 16; off; off >>= 1)
#pragma unroll
        for (int bb = 0; bb < 32; bb++)
            attnacc[bb] += __shfl_xor_sync(0xffffffffu, attnacc[bb], off);
    const int wid = tid >> 5, lane = tid & 31;
    if (lane == 0)
#pragma unroll
        for (int bb = 0; bb < 32; bb++) wred[wid][bb] = attnacc[bb];
    __syncthreads();
    if (tid < 32) {
        float s = 0.0f;
#pragma unroll
        for (int w = 0; w < 8; w++) s += wred[w][tid];
        g_attn[n * BATCH + tid] = s;
    }
}

// ---------------------------------------------------------------------------
// Kernel 5: softmax + weighted sum + final linear. CTA per b.
// ---------------------------------------------------------------------------
__global__ void __launch_bounds__(256) final_kernel(
    const float* __restrict__ out_note,
    const float* __restrict__ lin_w,
    const float* __restrict__ lin_b,
    float* __restrict__ out)
{
    __shared__ float sa[64];
    __shared__ float vec[512];
    __shared__ float stats[2];
    const int tid = threadIdx.x;
    const int b = blockIdx.x;

    if (tid < 64) sa[tid] = g_attn[tid * BATCH + b];
    __syncthreads();
    if (tid < 32) {
        const float v0 = sa[tid], v1 = sa[tid + 32];
        float m = fmaxf(v0, v1);
#pragma unroll
        for (int o = 16; o; o >>= 1) m = fmaxf(m, __shfl_xor_sync(0xffffffffu, m, o));
        float s = expf(v0 - m) + expf(v1 - m);
#pragma unroll
        for (int o = 16; o; o >>= 1) s += __shfl_xor_sync(0xffffffffu, s, o);
        if (tid == 0) { stats[0] = m; stats[1] = s; }
    }
    __syncthreads();
    if (tid < 64) {
        const float nv = expf(sa[tid] - stats[0]) / stats[1];
        sa[tid] = nv;
        out[OFF_NORM + b * 64 + tid] = nv;
    }
    __syncthreads();
#pragma unroll
    for (int dd = 0; dd < 2; dd++) {
        const int d = dd * 256 + tid;
        float acc = 0.0f;
#pragma unroll 8
        for (int n = 0; n < 64; n++)
            acc += sa[n] * out_note[(size_t)(n * BATCH + b) * 512 + d];
        vec[d] = acc;
        out[OFF_VEC + b * 512 + d] = acc;
    }
    __syncthreads();
    if (tid < 64) {
        const int c = tid >> 5, lane = tid & 31;
        float p = 0.0f;
#pragma unroll 4
        for (int i = lane; i < 512; i += 32) p += lin_w[c * 512 + i] * vec[i];
#pragma unroll
        for (int o = 16; o; o >>= 1) p += __shfl_xor_sync(0xffffffffu, p, o);
        if (lane == 0) out[OFF_FIN + b * 2 + c] = p + lin_b[c];
    }
}

// ---------------------------------------------------------------------------
// Launcher
// ---------------------------------------------------------------------------
extern "C" void kernel_launch(void* const* d_in, const int* in_sizes, int n_in,
                              void* d_out, int out_size)
{
    (void)in_sizes; (void)n_in; (void)out_size;
    const int*   mini_batch = (const int*)d_in[0];
    const float* hidden     = (const float*)d_in[1];
    const float* embed      = (const float*)d_in[2];
    const float* conv_w     = (const float*)d_in[3];
    const float* conv_b     = (const float*)d_in[4];
    const float* w_ih_f     = (const float*)d_in[5];
    const float* w_hh_f     = (const float*)d_in[6];
    const float* b_ih_f     = (const float*)d_in[7];
    const float* b_hh_f     = (const float*)d_in[8];
    const float* w_ih_b     = (const float*)d_in[9];
    const float* w_hh_b     = (const float*)d_in[10];
    const float* b_ih_b     = (const float*)d_in[11];
    const float* b_hh_b     = (const float*)d_in[12];
    const float* W_note     = (const float*)d_in[13];
    const float* bias_note  = (const float*)d_in[14];
    const float* proj_note  = (const float*)d_in[15];
    const float* lin_w      = (const float*)d_in[16];
    const float* lin_b      = (const float*)d_in[17];
    float* out = (float*)d_out;

    cudaFuncSetAttribute(conv_mma_kernel,
                         cudaFuncAttributeMaxDynamicSharedMemorySize, CONV_SMEM);
    cudaFuncSetAttribute(attn_kernel,
                         cudaFuncAttributeMaxDynamicSharedMemorySize, 65536);

    init_featmax_kernel<<<N_NOTES * BATCH, 256>>>();
    wsplit_kernel<<<384, 256>>>(conv_w);
    conv_mma_kernel<<<N_NOTES * BATCH * 2, 512, CONV_SMEM>>>(mini_batch, embed);
    conv_tail_kernel<<<N_NOTES, 256>>>(mini_batch, embed, conv_w);
    wnote_transpose_kernel<<<512, 256>>>(W_note);
    gi_kernel<<<128, 256>>>(w_ih_f, w_ih_b, b_ih_f, b_ih_b, conv_b);
    gru_kernel<<<64, 256>>>(w_hh_f, w_hh_b, b_hh_f, b_hh_b, hidden, out);
    attn_kernel<<<64, 256, 65536>>>(out, bias_note, proj_note);
    final_kernel<<<32, 256>>>(out, lin_w, lin_b, out);
}